// round 2
// baseline (speedup 1.0000x reference)
#include <cuda_runtime.h>

#define TOKENS   16
#define OUTS     32
#define CH       4
#define DIM      64
#define TILE_B   16
#define NTHREADS 512
#define PAD      68                      // floats per 64-d row (+4 pad: conflict-free lane tiling)

#define YS_FLOATS (TOKENS * TILE_B * PAD)    // 17408
#define WG_FLOATS (TOKENS * OUTS * PAD)      // 34816
#define SMEM_BYTES ((YS_FLOATS + WG_FLOATS) * 4 + TOKENS * CH * 8)   // 209408 B

typedef unsigned long long u64;

// Packed dual-FMA: {lo,hi} lanes independently (Blackwell f32x2)
__device__ __forceinline__ u64 ffma2(u64 a, u64 b, u64 c) {
    u64 d;
    asm("fma.rn.f32x2 %0, %1, %2, %3;" : "=l"(d) : "l"(a), "l"(b), "l"(c));
    return d;
}
__device__ __forceinline__ float f2lo(u64 v) { return __int_as_float((int)(unsigned)v); }
__device__ __forceinline__ float f2hi(u64 v) { return __int_as_float((int)(unsigned)(v >> 32)); }

__global__ __launch_bounds__(NTHREADS, 1)
void ftok_kernel(const float* __restrict__ x,    // [B, 4, 64]
                 const float* __restrict__ Wg,   // [16, 32, 64]
                 const float* __restrict__ bg,   // [16, 32]
                 const float* __restrict__ Wm,   // [16, 4]
                 float* __restrict__ out,        // [B, 512]
                 int ntiles)
{
    extern __shared__ float smem[];
    float* ys  = smem;                            // [t][row][PAD]
    float* wgs = smem + YS_FLOATS;                // [t][o][PAD]
    u64*   wmdup = (u64*)(smem + YS_FLOATS + WG_FLOATS);  // [t][c] duplicated-pair Wm

    const int tid = threadIdx.x;
    const int w   = tid >> 5;      // warp: produce batch row w; consume token w
    const int l   = tid & 31;
    const int rg  = l >> 2;        // 0..7  consume row group (rows rg, rg+8)
    const int og  = l & 3;         // 0..3  consume out group (outs og+4j)

    // --- one-time init: Wg -> padded smem (vectorized), dup-packed Wm ---
    {
        const float4* src = (const float4*)Wg;
        #pragma unroll
        for (int k = 0; k < (TOKENS * OUTS * DIM / 4) / NTHREADS; k++) {
            int idx = tid + k * NTHREADS;   // float4 index; 16 per (t,o) row
            int row = idx >> 4;
            int c4  = idx & 15;
            *(float4*)(wgs + row * PAD + c4 * 4) = src[idx];
        }
    }
    if (tid < TOKENS * CH) {
        unsigned int ui = __float_as_uint(Wm[tid]);
        wmdup[tid] = ((u64)ui << 32) | ui;
    }

    // Effective biases for this lane's 8 outputs: bg[t,o] * sum_c Wm[t,c]
    const float s_t = Wm[w * 4 + 0] + Wm[w * 4 + 1] + Wm[w * 4 + 2] + Wm[w * 4 + 3];
    float ceff[8];
    #pragma unroll
    for (int j = 0; j < 8; j++) ceff[j] = s_t * bg[w * OUTS + og + 4 * j];

    int tile = blockIdx.x;

    // Prologue: x registers for first tile (row w), d-pair (2l, 2l+1) per channel
    u64 xr[CH];
    if (tile < ntiles) {
        const u64* xp = (const u64*)(x + ((size_t)tile * TILE_B + w) * (CH * DIM));
        #pragma unroll
        for (int c = 0; c < CH; c++) xr[c] = xp[c * (DIM / 2) + l];
    }

    __syncthreads();  // wgs/wmdup visible

    for (; tile < ntiles; tile += gridDim.x) {
        // ---------- produce: y[t][row=w][2l,2l+1] for all 16 tokens ----------
        #pragma unroll
        for (int t = 0; t < TOKENS; t++) {
            const ulonglong2* mp = (const ulonglong2*)(wmdup + t * CH);
            ulonglong2 m01 = mp[0], m23 = mp[1];
            u64 acc = ffma2(m23.y, xr[3], 0ull);
            acc = ffma2(m23.x, xr[2], acc);
            acc = ffma2(m01.y, xr[1], acc);
            acc = ffma2(m01.x, xr[0], acc);
            ((u64*)(ys + (t * TILE_B + w) * PAD))[l] = acc;   // STS.64, conflict-free
        }

        // Prefetch x for this block's next tile (hides under consume)
        {
            int nt = tile + gridDim.x;
            if (nt < ntiles) {
                const u64* xp = (const u64*)(x + ((size_t)nt * TILE_B + w) * (CH * DIM));
                #pragma unroll
                for (int c = 0; c < CH; c++) xr[c] = xp[c * (DIM / 2) + l];
            }
        }

        __syncthreads();  // y ready

        // ---------- consume: token w, register-tiled 16x32 GEMM ----------
        u64 acc[2][8];
        #pragma unroll
        for (int i = 0; i < 2; i++)
            #pragma unroll
            for (int j = 0; j < 8; j++) acc[i][j] = 0ull;

        const float* yb = ys  + (w * TILE_B) * PAD;
        const float* wb = wgs + (w * OUTS)   * PAD;

        #pragma unroll 4
        for (int c = 0; c < DIM / 4; c++) {
            // y: 8 distinct rows per wavefront (128B useful, banks rg*4 -> perfect tiling)
            ulonglong2 yv0 = *(const ulonglong2*)(yb + (rg    ) * PAD + c * 4);
            ulonglong2 yv1 = *(const ulonglong2*)(yb + (rg + 8) * PAD + c * 4);
            #pragma unroll
            for (int j = 0; j < 8; j++) {
                // w: 4 distinct outs per wavefront (quads 0..3), reused for both rows
                ulonglong2 wv = *(const ulonglong2*)(wb + (og + 4 * j) * PAD + c * 4);
                acc[0][j] = ffma2(yv0.y, wv.y, ffma2(yv0.x, wv.x, acc[0][j]));
                acc[1][j] = ffma2(yv1.y, wv.y, ffma2(yv1.x, wv.x, acc[1][j]));
            }
        }

        // ---------- epilogue: reduce packed pairs, bias, relu, store ----------
        float* ob = out + ((size_t)tile * TILE_B) * (TOKENS * OUTS) + w * OUTS + og;
        #pragma unroll
        for (int i = 0; i < 2; i++) {
            #pragma unroll
            for (int j = 0; j < 8; j++) {
                float r = f2lo(acc[i][j]) + f2hi(acc[i][j]) + ceff[j];
                r = fmaxf(r, 0.0f);
                ob[(size_t)(rg + 8 * i) * (TOKENS * OUTS) + 4 * j] = r;
            }
        }

        __syncthreads();  // protect ys before next produce overwrites
    }
}

extern "C" void kernel_launch(void* const* d_in, const int* in_sizes, int n_in,
                              void* d_out, int out_size) {
    const float* x  = (const float*)d_in[0];
    const float* Wg = (const float*)d_in[1];
    const float* bg = (const float*)d_in[2];
    const float* Wm = (const float*)d_in[3];
    float* out = (float*)d_out;

    const int B      = in_sizes[0] / (CH * DIM);   // 32768
    const int ntiles = B / TILE_B;                 // 2048

    cudaFuncSetAttribute(ftok_kernel,
                         cudaFuncAttributeMaxDynamicSharedMemorySize, SMEM_BYTES);

    int dev = 0, sms = 148;
    cudaGetDevice(&dev);
    cudaDeviceGetAttribute(&sms, cudaDevAttrMultiProcessorCount, dev);
    int grid = sms < ntiles ? sms : ntiles;

    ftok_kernel<<<grid, NTHREADS, SMEM_BYTES>>>(x, Wg, bg, Wm, out, ntiles);
}

// round 4
// speedup vs baseline: 1.0198x; 1.0198x over previous
#include <cuda_runtime.h>
#include <cuda_bf16.h>

// ===================== problem constants =====================
#define KDIM    256            // c*64+d
#define NDIM    512            // t*32+o
#define MTILE   128
#define NTILE   256
#define THREADS 512

// ===================== device scratch (no allocs allowed) =====================
__device__ __nv_bfloat16 g_w2h[NDIM * KDIM];
__device__ __nv_bfloat16 g_w2l[NDIM * KDIM];
__device__ float         g_beff[NDIM];

// ===================== smem layout =====================
// pitch per 128-element K chunk row: 136 bf16 = 272 bytes (272/4 = 68 == 4 mod 32
// -> ldmatrix 8-row phases hit distinct banks)
#define PITCH   272
#define SM_AH   0                                  // A hi: 128 rows
#define SM_AL   (SM_AH + MTILE * PITCH)            // 34816
#define SM_BH   (SM_AL + MTILE * PITCH)            // 69632, B hi: 256 rows
#define SM_BL   (SM_BH + NTILE * PITCH)            // 139264
#define SM_BEFF (SM_BL + NTILE * PITCH)            // 208896
#define SMEM_TOTAL (SM_BEFF + NTILE * 4)           // 209920

// ===================== PTX helpers =====================
__device__ __forceinline__ unsigned smem_u32(const void* p) {
    unsigned a;
    asm("{ .reg .u64 t; cvta.to.shared.u64 t, %1; cvt.u32.u64 %0, t; }" : "=r"(a) : "l"(p));
    return a;
}
__device__ __forceinline__ void ldmx4(unsigned* r, unsigned addr) {
    asm volatile("ldmatrix.sync.aligned.m8n8.x4.shared.b16 {%0,%1,%2,%3}, [%4];"
                 : "=r"(r[0]), "=r"(r[1]), "=r"(r[2]), "=r"(r[3]) : "r"(addr));
}
__device__ __forceinline__ void ldmx2(unsigned* r, unsigned addr) {
    asm volatile("ldmatrix.sync.aligned.m8n8.x2.shared.b16 {%0,%1}, [%2];"
                 : "=r"(r[0]), "=r"(r[1]) : "r"(addr));
}
__device__ __forceinline__ void mma16816(float* d, const unsigned* a, const unsigned* b) {
    asm volatile("mma.sync.aligned.m16n8k16.row.col.f32.bf16.bf16.f32 "
                 "{%0,%1,%2,%3}, {%4,%5,%6,%7}, {%8,%9}, {%0,%1,%2,%3};"
                 : "+f"(d[0]), "+f"(d[1]), "+f"(d[2]), "+f"(d[3])
                 : "r"(a[0]), "r"(a[1]), "r"(a[2]), "r"(a[3]), "r"(b[0]), "r"(b[1]));
}

// ===================== prep: fused W2 hi/lo + effective bias =====================
__global__ void prep_kernel(const float* __restrict__ Wg, const float* __restrict__ bg,
                            const float* __restrict__ Wm) {
    int e = blockIdx.x * blockDim.x + threadIdx.x;
    if (e < NDIM * KDIM) {
        int n = e >> 8, k = e & 255;
        int t = n >> 5, o = n & 31;
        int c = k >> 6, d = k & 63;
        float v = Wm[t * 4 + c] * Wg[(t * 32 + o) * 64 + d];
        __nv_bfloat16 h = __float2bfloat16(v);
        g_w2h[e] = h;
        g_w2l[e] = __float2bfloat16(v - __bfloat162float(h));
    }
    if (e < NDIM) {
        int t = e >> 5, o = e & 31;
        float s = Wm[t * 4] + Wm[t * 4 + 1] + Wm[t * 4 + 2] + Wm[t * 4 + 3];
        g_beff[e] = s * bg[t * 32 + o];
    }
}

// ===================== main GEMM: out = relu(X @ W2^T + beff) =====================
__global__ __launch_bounds__(THREADS, 1)
void gemm_kernel(const float* __restrict__ x, float* __restrict__ out) {
    extern __shared__ char smem[];
    const unsigned sb = smem_u32(smem);
    const int tid = threadIdx.x;
    const int wid = tid >> 5, l = tid & 31;
    const int mt  = blockIdx.x >> 1, ntl = blockIdx.x & 1;
    const int wm  = wid & 3;          // m block: 32 rows
    const int wn  = wid >> 2;         // n block: 64 cols

    float acc[2][8][4];
    #pragma unroll
    for (int i = 0; i < 2; i++)
        #pragma unroll
        for (int j = 0; j < 8; j++)
            #pragma unroll
            for (int q = 0; q < 4; q++) acc[i][j][q] = 0.f;

    if (tid < NTILE) ((float*)(smem + SM_BEFF))[tid] = g_beff[ntl * NTILE + tid];

    // precomputed ldmatrix lane addresses (row/k-half pattern fixed per lane)
    const unsigned a_lane_base =
        sb + SM_AH + (unsigned)((wm * 32 + (l & 15)) * PITCH) + (unsigned)((l >> 4) * 16);
    const unsigned b_lane_base =
        sb + SM_BH + (unsigned)((wn * 64 + (l & 7)) * PITCH) + (unsigned)(((l >> 3) & 1) * 16);

    #pragma unroll 1
    for (int kh = 0; kh < 2; kh++) {
        // ---- stage A: x fp32 [128,128] -> bf16 hi/lo, smem ----
        #pragma unroll
        for (int i = 0; i < 8; i++) {
            int f4 = tid + i * THREADS;            // 4096 float4
            int m = f4 >> 5, k4 = f4 & 31;         // k = 4*k4 in chunk
            float4 v = *(const float4*)(x + ((size_t)(mt * MTILE + m)) * KDIM + kh * 128 + k4 * 4);
            __nv_bfloat162 h0 = __float22bfloat162_rn(make_float2(v.x, v.y));
            __nv_bfloat162 h1 = __float22bfloat162_rn(make_float2(v.z, v.w));
            __nv_bfloat162 l0 = __float22bfloat162_rn(
                make_float2(v.x - __low2float(h0), v.y - __high2float(h0)));
            __nv_bfloat162 l1 = __float22bfloat162_rn(
                make_float2(v.z - __low2float(h1), v.w - __high2float(h1)));
            unsigned off = (unsigned)(m * PITCH + k4 * 8);
            *(uint2*)(smem + SM_AH + off) = make_uint2(*(unsigned*)&h0, *(unsigned*)&h1);
            *(uint2*)(smem + SM_AL + off) = make_uint2(*(unsigned*)&l0, *(unsigned*)&l1);
        }
        // ---- stage B: W2 hi/lo bf16 [256,128] -> smem ----
        #pragma unroll
        for (int i = 0; i < 8; i++) {
            int u = tid + i * THREADS;             // 4096 uint4
            int n = u >> 4, j = u & 15;            // k = 8*j
            size_t src = ((size_t)(ntl * NTILE + n)) * KDIM + kh * 128 + j * 8;
            unsigned off = (unsigned)(n * PITCH + j * 16);
            *(uint4*)(smem + SM_BH + off) = *(const uint4*)(g_w2h + src);
            *(uint4*)(smem + SM_BL + off) = *(const uint4*)(g_w2l + src);
        }
        __syncthreads();

        // ---- compute: 8 k16-steps, 3-term bf16 split ----
        #pragma unroll 2
        for (int ks = 0; ks < 8; ks++) {
            unsigned ah[2][4], al[2][4];
            #pragma unroll
            for (int i = 0; i < 2; i++) {
                unsigned aaddr = a_lane_base + (unsigned)(i * 16 * PITCH + ks * 32);
                ldmx4(ah[i], aaddr);
                ldmx4(al[i], aaddr + (SM_AL - SM_AH));
            }
            #pragma unroll
            for (int j = 0; j < 8; j++) {
                unsigned baddr = b_lane_base + (unsigned)(j * 8 * PITCH + ks * 32);
                unsigned bh[2], bl[2];
                ldmx2(bh, baddr);
                ldmx2(bl, baddr + (SM_BL - SM_BH));
                #pragma unroll
                for (int i = 0; i < 2; i++) {
                    mma16816(acc[i][j], ah[i], bh);   // hh
                    mma16816(acc[i][j], ah[i], bl);   // hl
                    mma16816(acc[i][j], al[i], bh);   // lh
                }
            }
        }
        __syncthreads();
    }

    // ---- epilogue: bias + relu, float2 stores ----
    const float* beff_s = (const float*)(smem + SM_BEFF);
    const int n_lane = wn * 64 + 2 * (l & 3);
    const int m_lane = mt * MTILE + wm * 32 + (l >> 2);
    #pragma unroll
    for (int i = 0; i < 2; i++) {
        #pragma unroll
        for (int j = 0; j < 8; j++) {
            int n = n_lane + j * 8;
            float2 bv = *(const float2*)(beff_s + n);
            float2 r0, r1;
            r0.x = fmaxf(acc[i][j][0] + bv.x, 0.f);
            r0.y = fmaxf(acc[i][j][1] + bv.y, 0.f);
            r1.x = fmaxf(acc[i][j][2] + bv.x, 0.f);
            r1.y = fmaxf(acc[i][j][3] + bv.y, 0.f);
            size_t row0 = (size_t)(m_lane + i * 16);
            *(float2*)(out + row0 * NDIM + ntl * NTILE + n) = r0;
            *(float2*)(out + (row0 + 8) * NDIM + ntl * NTILE + n) = r1;
        }
    }
}

// ===================== launch =====================
extern "C" void kernel_launch(void* const* d_in, const int* in_sizes, int n_in,
                              void* d_out, int out_size) {
    const float* x  = (const float*)d_in[0];
    const float* Wg = (const float*)d_in[1];
    const float* bg = (const float*)d_in[2];
    const float* Wm = (const float*)d_in[3];
    float* out = (float*)d_out;

    const int B = in_sizes[0] / KDIM;        // 32768
    const int mtiles = B / MTILE;            // 256

    prep_kernel<<<(NDIM * KDIM + 255) / 256, 256>>>(Wg, bg, Wm);

    cudaFuncSetAttribute(gemm_kernel,
                         cudaFuncAttributeMaxDynamicSharedMemorySize, SMEM_TOTAL);
    gemm_kernel<<<mtiles * 2, THREADS, SMEM_TOTAL>>>(x, out);
}

// round 5
// speedup vs baseline: 1.3299x; 1.3040x over previous
#include <cuda_runtime.h>
#include <cuda_bf16.h>

// ===================== problem constants =====================
#define KDIM    256            // c*64+d
#define NDIM    512            // t*32+o
#define MTILE   128
#define NTILE   128            // per-CTA N slice (ntl in 0..3)
#define THREADS 512
#define KC      64             // K chunk
#define NCHUNK  4

// ===================== device scratch =====================
__device__ __nv_bfloat16 g_w2h[NDIM * KDIM];
__device__ __nv_bfloat16 g_w2l[NDIM * KDIM];
__device__ float         g_beff[NDIM];

// ===================== smem layout =====================
// pitch per 64-element K-chunk row: 72 bf16 = 144 B (144/4 = 36 ≡ 4 mod 32 -> conflict-free)
#define PITCH    144
#define HALFOFF  (128 * PITCH)          // 18432: hi->lo offset within a chunk
#define CHSTRIDE (2 * HALFOFF)          // 36864: one chunk (hi+lo)
#define SM_B     0                       // B: 4 chunks resident     (147456)
#define SM_A     (NCHUNK * CHSTRIDE)     // A: 2 buffers             (73728)
#define SM_BEFF  (SM_A + 2 * CHSTRIDE)   // 221184
#define SMEM_TOTAL (SM_BEFF + NTILE * 4) // 221696

// ===================== PTX helpers =====================
__device__ __forceinline__ unsigned smem_u32(const void* p) {
    unsigned a;
    asm("{ .reg .u64 t; cvta.to.shared.u64 t, %1; cvt.u32.u64 %0, t; }" : "=r"(a) : "l"(p));
    return a;
}
__device__ __forceinline__ void ldmx4(unsigned* r, unsigned addr) {
    asm volatile("ldmatrix.sync.aligned.m8n8.x4.shared.b16 {%0,%1,%2,%3}, [%4];"
                 : "=r"(r[0]), "=r"(r[1]), "=r"(r[2]), "=r"(r[3]) : "r"(addr));
}
__device__ __forceinline__ void ldmx2(unsigned* r, unsigned addr) {
    asm volatile("ldmatrix.sync.aligned.m8n8.x2.shared.b16 {%0,%1}, [%2];"
                 : "=r"(r[0]), "=r"(r[1]) : "r"(addr));
}
__device__ __forceinline__ void mma16816(float* d, const unsigned* a, const unsigned* b) {
    asm volatile("mma.sync.aligned.m16n8k16.row.col.f32.bf16.bf16.f32 "
                 "{%0,%1,%2,%3}, {%4,%5,%6,%7}, {%8,%9}, {%0,%1,%2,%3};"
                 : "+f"(d[0]), "+f"(d[1]), "+f"(d[2]), "+f"(d[3])
                 : "r"(a[0]), "r"(a[1]), "r"(a[2]), "r"(a[3]), "r"(b[0]), "r"(b[1]));
}

// ===================== prep: fused W2 hi/lo + effective bias =====================
__global__ void prep_kernel(const float* __restrict__ Wg, const float* __restrict__ bg,
                            const float* __restrict__ Wm) {
    int e = blockIdx.x * blockDim.x + threadIdx.x;
    if (e < NDIM * KDIM) {
        int n = e >> 8, k = e & 255;
        int t = n >> 5, o = n & 31;
        int c = k >> 6, d = k & 63;
        float v = Wm[t * 4 + c] * Wg[(t * 32 + o) * 64 + d];
        __nv_bfloat16 h = __float2bfloat16(v);
        g_w2h[e] = h;
        g_w2l[e] = __float2bfloat16(v - __bfloat162float(h));
    }
    if (e < NDIM) {
        int t = e >> 5, o = e & 31;
        float s = Wm[t * 4] + Wm[t * 4 + 1] + Wm[t * 4 + 2] + Wm[t * 4 + 3];
        g_beff[e] = s * bg[t * 32 + o];
    }
}

// ===================== persistent GEMM: out = relu(X @ W2^T + beff) =====================
__global__ __launch_bounds__(THREADS, 1)
void gemm_kernel(const float* __restrict__ x, float* __restrict__ out,
                 int ntm, int mstride) {
    extern __shared__ char smem[];
    const unsigned sb = smem_u32(smem);
    const int tid = threadIdx.x, wid = tid >> 5, l = tid & 31;
    const int ntl = blockIdx.x & 3;           // fixed N slice per CTA
    int       mt  = blockIdx.x >> 2;          // starting M tile
    const int wm  = wid & 3;                  // 32 rows per warp
    const int wn  = wid >> 2;                 // 32 cols per warp

    // ---- one-time: stage resident B (hi/lo, all 4 K chunks) + beff ----
    #pragma unroll
    for (int i = 0; i < 8; i++) {
        int u = tid + i * THREADS;            // 4096 uint4 per half
        int n = u >> 5, j = u & 31;           // k = j*8
        size_t src = ((size_t)(ntl * NTILE + n)) * KDIM + j * 8;
        unsigned off = (unsigned)((j >> 3) * CHSTRIDE + n * PITCH + (j & 7) * 16);
        *(uint4*)(smem + SM_B + off)           = *(const uint4*)(g_w2h + src);
        *(uint4*)(smem + SM_B + off + HALFOFF) = *(const uint4*)(g_w2l + src);
    }
    if (tid < NTILE) ((float*)(smem + SM_BEFF))[tid] = g_beff[ntl * NTILE + tid];

    // ---- prologue: LDG chunk 0 of first tile into regs ----
    float4 xr[4];
    if (mt < ntm) {
        #pragma unroll
        for (int i = 0; i < 4; i++) {
            int f4 = tid + i * THREADS;       // 2048 float4 per chunk
            int m = f4 >> 4, k4 = f4 & 15;
            xr[i] = *(const float4*)(x + ((size_t)(mt * MTILE + m)) * KDIM + k4 * 4);
        }
    }

    const unsigned a_lane = sb + SM_A +
        (unsigned)((wm * 32 + (l & 15)) * PITCH + (l >> 4) * 16);
    const unsigned b_lane = sb + SM_B +
        (unsigned)((wn * 32 + (l & 7)) * PITCH + ((l >> 3) & 1) * 16);
    const float* beff_s = (const float*)(smem + SM_BEFF);

    int buf = 0;
    while (mt < ntm) {
        float acc[2][4][4];
        #pragma unroll
        for (int i = 0; i < 2; i++)
            #pragma unroll
            for (int j = 0; j < 4; j++)
                #pragma unroll
                for (int q = 0; q < 4; q++) acc[i][j][q] = 0.f;

        #pragma unroll 1
        for (int kc = 0; kc < NCHUNK; kc++) {
            // ---- STS: regs -> A[buf] as bf16 hi/lo ----
            #pragma unroll
            for (int i = 0; i < 4; i++) {
                int f4 = tid + i * THREADS;
                int m = f4 >> 4, k4 = f4 & 15;
                float4 v = xr[i];
                __nv_bfloat162 h0 = __float22bfloat162_rn(make_float2(v.x, v.y));
                __nv_bfloat162 h1 = __float22bfloat162_rn(make_float2(v.z, v.w));
                __nv_bfloat162 l0 = __float22bfloat162_rn(
                    make_float2(v.x - __low2float(h0), v.y - __high2float(h0)));
                __nv_bfloat162 l1 = __float22bfloat162_rn(
                    make_float2(v.z - __low2float(h1), v.w - __high2float(h1)));
                unsigned off = (unsigned)(buf * CHSTRIDE + m * PITCH + k4 * 8);
                *(uint2*)(smem + SM_A + off) =
                    make_uint2(*(unsigned*)&h0, *(unsigned*)&h1);
                *(uint2*)(smem + SM_A + off + HALFOFF) =
                    make_uint2(*(unsigned*)&l0, *(unsigned*)&l1);
            }
            __syncthreads();

            // ---- LDG next chunk (hides under compute) ----
            int nkc = kc + 1, nmt = mt;
            if (nkc == NCHUNK) { nkc = 0; nmt = mt + mstride; }
            if (nmt < ntm) {
                #pragma unroll
                for (int i = 0; i < 4; i++) {
                    int f4 = tid + i * THREADS;
                    int m = f4 >> 4, k4 = f4 & 15;
                    xr[i] = *(const float4*)(x + ((size_t)(nmt * MTILE + m)) * KDIM
                                             + nkc * KC + k4 * 4);
                }
            }

            // ---- compute: 4 k16-steps, 3-term split ----
            const unsigned ab = a_lane + (unsigned)(buf * CHSTRIDE);
            const unsigned bb = b_lane + (unsigned)(kc * CHSTRIDE);
            #pragma unroll
            for (int ks = 0; ks < 4; ks++) {
                unsigned ah[2][4], al[2][4];
                #pragma unroll
                for (int i = 0; i < 2; i++) {
                    unsigned a = ab + (unsigned)(i * 16 * PITCH + ks * 32);
                    ldmx4(ah[i], a);
                    ldmx4(al[i], a + HALFOFF);
                }
                #pragma unroll
                for (int j = 0; j < 4; j++) {
                    unsigned b = bb + (unsigned)(j * 8 * PITCH + ks * 32);
                    unsigned bh[2], bl[2];
                    ldmx2(bh, b);
                    ldmx2(bl, b + HALFOFF);
                    #pragma unroll
                    for (int i = 0; i < 2; i++) {
                        mma16816(acc[i][j], ah[i], bh);   // hh
                        mma16816(acc[i][j], ah[i], bl);   // hl
                        mma16816(acc[i][j], al[i], bh);   // lh
                    }
                }
            }
            buf ^= 1;
        }

        // ---- epilogue: bias + relu, float2 stores ----
        const int m0 = mt * MTILE + wm * 32 + (l >> 2);
        #pragma unroll
        for (int i = 0; i < 2; i++) {
            #pragma unroll
            for (int j = 0; j < 4; j++) {
                int n = wn * 32 + j * 8 + 2 * (l & 3);
                float2 bv = *(const float2*)(beff_s + n);
                float2 r0, r1;
                r0.x = fmaxf(acc[i][j][0] + bv.x, 0.f);
                r0.y = fmaxf(acc[i][j][1] + bv.y, 0.f);
                r1.x = fmaxf(acc[i][j][2] + bv.x, 0.f);
                r1.y = fmaxf(acc[i][j][3] + bv.y, 0.f);
                size_t row = (size_t)(m0 + i * 16);
                *(float2*)(out + row * NDIM + ntl * NTILE + n) = r0;
                *(float2*)(out + (row + 8) * NDIM + ntl * NTILE + n) = r1;
            }
        }
        mt += mstride;
    }
}

// ===================== launch =====================
extern "C" void kernel_launch(void* const* d_in, const int* in_sizes, int n_in,
                              void* d_out, int out_size) {
    const float* x  = (const float*)d_in[0];
    const float* Wg = (const float*)d_in[1];
    const float* bg = (const float*)d_in[2];
    const float* Wm = (const float*)d_in[3];
    float* out = (float*)d_out;

    const int B   = in_sizes[0] / KDIM;      // 32768
    const int ntm = B / MTILE;               // 256

    prep_kernel<<<(NDIM * KDIM + 255) / 256, 256>>>(Wg, bg, Wm);

    cudaFuncSetAttribute(gemm_kernel,
                         cudaFuncAttributeMaxDynamicSharedMemorySize, SMEM_TOTAL);

    int dev = 0, sms = 148;
    cudaGetDevice(&dev);
    cudaDeviceGetAttribute(&sms, cudaDevAttrMultiProcessorCount, dev);
    int grid = sms & ~3;                     // multiple of 4 (one ntl group per CTA)
    if (grid < 4) grid = 4;
    int mstride = grid >> 2;

    gemm_kernel<<<grid, THREADS, SMEM_TOTAL>>>(x, out, ntm, mstride);
}

// round 7
// speedup vs baseline: 1.5864x; 1.1929x over previous
#include <cuda_runtime.h>
#include <cuda_bf16.h>

// ===================== problem constants =====================
#define KDIM    256            // x row: c*64+d
#define NDIM    512            // t*32+o
#define MTILE   128
#define THREADS 512

// ===================== device scratch =====================
__device__ __nv_bfloat16 g_wgh[16 * 32 * 64];
__device__ __nv_bfloat16 g_wgl[16 * 32 * 64];
__device__ float         g_beff[NDIM];

// ===================== smem layout =====================
#define PITCH    144                       // 64 bf16 + 8 pad (16B-aligned, conflict-free)
#define WGHALF   (512 * PITCH)             // 73728 (16 tokens x 32 rows)
#define SM_WG    0                         // hi at 0, lo at +WGHALF  (147456)
#define YHALF    (128 * PITCH)             // 18432
#define YBUF     (2 * YHALF)               // 36864 (hi+lo)
#define SM_Y     (2 * WGHALF)              // 147456, two buffers
#define SM_BEFF  (SM_Y + 2 * YBUF)         // 221184
#define SM_WM    (SM_BEFF + NDIM * 4)      // 223232
#define SMEM_TOTAL (SM_WM + 64 * 4)        // 223488

typedef unsigned long long u64;

// ===================== PTX helpers (validated in prior rounds) =====================
__device__ __forceinline__ unsigned smem_u32(const void* p) {
    unsigned a;
    asm("{ .reg .u64 t; cvta.to.shared.u64 t, %1; cvt.u32.u64 %0, t; }" : "=r"(a) : "l"(p));
    return a;
}
__device__ __forceinline__ u64 ffma2(u64 a, u64 b, u64 c) {
    u64 d;
    asm("fma.rn.f32x2 %0, %1, %2, %3;" : "=l"(d) : "l"(a), "l"(b), "l"(c));
    return d;
}
__device__ __forceinline__ u64 fmul2(u64 a, u64 b) {
    u64 d;
    asm("mul.rn.f32x2 %0, %1, %2;" : "=l"(d) : "l"(a), "l"(b));
    return d;
}
__device__ __forceinline__ void ldmx4(unsigned* r, unsigned addr) {
    asm volatile("ldmatrix.sync.aligned.m8n8.x4.shared.b16 {%0,%1,%2,%3}, [%4];"
                 : "=r"(r[0]), "=r"(r[1]), "=r"(r[2]), "=r"(r[3]) : "r"(addr));
}
__device__ __forceinline__ void mma16816(float* d, const unsigned* a, const unsigned* b) {
    asm volatile("mma.sync.aligned.m16n8k16.row.col.f32.bf16.bf16.f32 "
                 "{%0,%1,%2,%3}, {%4,%5,%6,%7}, {%8,%9}, {%0,%1,%2,%3};"
                 : "+f"(d[0]), "+f"(d[1]), "+f"(d[2]), "+f"(d[3])
                 : "r"(a[0]), "r"(a[1]), "r"(a[2]), "r"(a[3]), "r"(b[0]), "r"(b[1]));
}

// ===================== prep: Wg hi/lo split + effective bias =====================
__global__ void prep_kernel(const float* __restrict__ Wg, const float* __restrict__ bg,
                            const float* __restrict__ Wm) {
    int e = blockIdx.x * blockDim.x + threadIdx.x;
    if (e < 16 * 32 * 64) {
        float v = Wg[e];
        __nv_bfloat16 h = __float2bfloat16(v);
        g_wgh[e] = h;
        g_wgl[e] = __float2bfloat16(v - __bfloat162float(h));
    }
    if (e < NDIM) {
        int t = e >> 5;
        float s = Wm[t * 4] + Wm[t * 4 + 1] + Wm[t * 4 + 2] + Wm[t * 4 + 3];
        g_beff[e] = s * bg[e];
    }
}

// ===================== main kernel =====================
__global__ __launch_bounds__(THREADS, 1)
void ftok_kernel(const float* __restrict__ x, float* __restrict__ out,
                 const float* __restrict__ Wm) {
    extern __shared__ char smem[];
    const unsigned sb = smem_u32(smem);
    const int tid = threadIdx.x, wid = tid >> 5, l = tid & 31;
    const int mt  = blockIdx.x;
    const int wm  = wid & 7;                  // 16 rows per warp
    const int wn  = wid >> 3;                 // 16 cols per warp
    const int m   = tid >> 2;                 // stage1 row (0..127)
    const int dq  = tid & 3;                  // stage1 d-quarter (16 d's)

    // ---- one-time staging: Wg hi/lo (pitch 144), beff, Wm ----
    // 512 rows x 8 uint4 per half = 4096 uint4 -> 8 iterations of 512 threads
    #pragma unroll
    for (int i = 0; i < 8; i++) {
        int u = tid + i * THREADS;            // 4096 uint4 per half
        int row = u >> 3, j = u & 7;          // row = t*32+n, k = 8j
        unsigned off = (unsigned)(row * PITCH + j * 16);
        *(uint4*)(smem + SM_WG + off)          = ((const uint4*)g_wgh)[u];
        *(uint4*)(smem + SM_WG + off + WGHALF) = ((const uint4*)g_wgl)[u];
    }
    ((float*)(smem + SM_BEFF))[tid] = g_beff[tid];
    if (tid < 64) ((float*)(smem + SM_WM))[tid] = Wm[tid];

    // ---- x -> registers: thread owns (m, dq): x[m][c*64 + dq*16 + 0..15], all c ----
    float4 xr[16];
    {
        const float* xrow = x + ((size_t)(mt * MTILE + m)) * KDIM + dq * 16;
        #pragma unroll
        for (int c = 0; c < 4; c++)
            #pragma unroll
            for (int e4 = 0; e4 < 4; e4++)
                xr[c * 4 + e4] = *(const float4*)(xrow + c * 64 + e4 * 4);
    }

    __syncthreads();

    const float4* wm_s  = (const float4*)(smem + SM_WM);
    const float*  beffs = (const float*)(smem + SM_BEFF);
    const unsigned ya_base = sb + SM_Y +
        (unsigned)((wm * 16 + (l & 15)) * PITCH + (l >> 4) * 16);
    const unsigned ba_base = sb + SM_WG +
        (unsigned)(((wn * 16 + (l & 7) + ((l >> 4) & 1) * 8)) * PITCH +
                   ((l >> 3) & 1) * 16);
    const unsigned ysts = (unsigned)(m * PITCH + dq * 32);

    // ---- stage1: produce y[t] (bf16 hi/lo) into buffer b ----
    auto stage1 = [&](int t, int b) {
        float4 wmv = wm_s[t];
        u64 wmd[4];
        {
            unsigned w0 = __float_as_uint(wmv.x), w1 = __float_as_uint(wmv.y);
            unsigned w2 = __float_as_uint(wmv.z), w3 = __float_as_uint(wmv.w);
            wmd[0] = ((u64)w0 << 32) | w0;  wmd[1] = ((u64)w1 << 32) | w1;
            wmd[2] = ((u64)w2 << 32) | w2;  wmd[3] = ((u64)w3 << 32) | w3;
        }
        unsigned hw[8], lw[8];
        #pragma unroll
        for (int p = 0; p < 8; p++) {
            const int e4 = p >> 1, hi = p & 1;
            u64 x0 = hi ? ((const ulonglong2*)&xr[0 * 4 + e4])->y
                        : ((const ulonglong2*)&xr[0 * 4 + e4])->x;
            u64 x1 = hi ? ((const ulonglong2*)&xr[1 * 4 + e4])->y
                        : ((const ulonglong2*)&xr[1 * 4 + e4])->x;
            u64 x2 = hi ? ((const ulonglong2*)&xr[2 * 4 + e4])->y
                        : ((const ulonglong2*)&xr[2 * 4 + e4])->x;
            u64 x3 = hi ? ((const ulonglong2*)&xr[3 * 4 + e4])->y
                        : ((const ulonglong2*)&xr[3 * 4 + e4])->x;
            u64 acc = fmul2(wmd[0], x0);
            acc = ffma2(wmd[1], x1, acc);
            acc = ffma2(wmd[2], x2, acc);
            acc = ffma2(wmd[3], x3, acc);
            float ylo = __uint_as_float((unsigned)acc);
            float yhi = __uint_as_float((unsigned)(acc >> 32));
            __nv_bfloat162 h2 = __float22bfloat162_rn(make_float2(ylo, yhi));
            unsigned h = *(unsigned*)&h2;
            float hflo = __uint_as_float(h << 16);
            float hfhi = __uint_as_float(h & 0xffff0000u);
            __nv_bfloat162 l2 =
                __float22bfloat162_rn(make_float2(ylo - hflo, yhi - hfhi));
            hw[p] = h;
            lw[p] = *(unsigned*)&l2;
        }
        char* yb = smem + SM_Y + b * YBUF + ysts;
        *(uint4*)(yb)          = make_uint4(hw[0], hw[1], hw[2], hw[3]);
        *(uint4*)(yb + 16)     = make_uint4(hw[4], hw[5], hw[6], hw[7]);
        *(uint4*)(yb + YHALF)      = make_uint4(lw[0], lw[1], lw[2], lw[3]);
        *(uint4*)(yb + YHALF + 16) = make_uint4(lw[4], lw[5], lw[6], lw[7]);
    };

    stage1(0, 0);
    __syncthreads();

    int buf = 0;
    #pragma unroll 1
    for (int t = 0; t < 16; t++) {
        if (t < 15) stage1(t + 1, buf ^ 1);

        // ---- stage2: token-t GEMM [128m x 32n, K=64], 3-term split ----
        float acc[2][4];
        #pragma unroll
        for (int j = 0; j < 2; j++)
            #pragma unroll
            for (int q = 0; q < 4; q++) acc[j][q] = 0.f;

        const unsigned ya = ya_base + (unsigned)(buf * YBUF);
        const unsigned ba = ba_base + (unsigned)(t * 32 * PITCH);
        #pragma unroll
        for (int ks = 0; ks < 4; ks++) {
            unsigned ah[4], al[4], bh[4], bl[4];
            ldmx4(ah, ya + ks * 32);
            ldmx4(al, ya + ks * 32 + YHALF);
            ldmx4(bh, ba + ks * 32);
            ldmx4(bl, ba + ks * 32 + WGHALF);
            mma16816(acc[0], ah, bh);      // hh, n-tile 0
            mma16816(acc[1], ah, bh + 2);  // hh, n-tile 1
            mma16816(acc[0], ah, bl);      // hl
            mma16816(acc[1], ah, bl + 2);
            mma16816(acc[0], al, bh);      // lh
            mma16816(acc[1], al, bh + 2);
        }

        // ---- epilogue: bias + relu + store ----
        const int r0 = wm * 16 + (l >> 2);
        #pragma unroll
        for (int j = 0; j < 2; j++) {
            int n = wn * 16 + j * 8 + 2 * (l & 3);
            float2 bv = *(const float2*)(beffs + t * 32 + n);
            float2 v0, v1;
            v0.x = fmaxf(acc[j][0] + bv.x, 0.f);
            v0.y = fmaxf(acc[j][1] + bv.y, 0.f);
            v1.x = fmaxf(acc[j][2] + bv.x, 0.f);
            v1.y = fmaxf(acc[j][3] + bv.y, 0.f);
            size_t row = (size_t)(mt * MTILE + r0);
            *(float2*)(out + row * NDIM + t * 32 + n) = v0;
            *(float2*)(out + (row + 8) * NDIM + t * 32 + n) = v1;
        }

        __syncthreads();
        buf ^= 1;
    }
}

// ===================== launch =====================
extern "C" void kernel_launch(void* const* d_in, const int* in_sizes, int n_in,
                              void* d_out, int out_size) {
    const float* x  = (const float*)d_in[0];
    const float* Wg = (const float*)d_in[1];
    const float* bg = (const float*)d_in[2];
    const float* Wm = (const float*)d_in[3];
    float* out = (float*)d_out;

    const int B   = in_sizes[0] / KDIM;      // 32768
    const int ntm = B / MTILE;               // 256

    prep_kernel<<<(16 * 32 * 64 + 255) / 256, 256>>>(Wg, bg, Wm);

    cudaFuncSetAttribute(ftok_kernel,
                         cudaFuncAttributeMaxDynamicSharedMemorySize, SMEM_TOTAL);
    ftok_kernel<<<ntm, THREADS, SMEM_TOTAL>>>(x, out, Wm);
}

// round 8
// speedup vs baseline: 2.1536x; 1.3575x over previous
#include <cuda_runtime.h>
#include <cuda_fp16.h>

// ===================== problem constants =====================
#define KDIM    256            // x row: c*64+d
#define NDIM    512            // t*32+o
#define MTILE   128
#define THREADS 512

// ===================== device scratch =====================
__device__ __half g_wgh[16 * 32 * 64];
__device__ __half g_wgl[16 * 32 * 64];
__device__ float  g_beff[NDIM];

// ===================== smem layout =====================
#define PITCH    144                       // 64 fp16 (128B) + 16B pad: conflict-free
#define WGHALF   (512 * PITCH)             // 73728 per half (16 tokens x 32 rows)
#define SM_WG    0                         // hi at 0, lo at +WGHALF    (147456)
#define YTOK     (128 * PITCH)             // 18432 per token (fp16, single)
#define SM_Y     (2 * WGHALF)              // 4 token slots             (73728)
#define SM_BEFF  (SM_Y + 4 * YTOK)         // 221184
#define SM_WM    (SM_BEFF + NDIM * 4)      // 223232
#define SMEM_TOTAL (SM_WM + 64 * 4)        // 223488 (fits; same as R7)

typedef unsigned long long u64;

// ===================== PTX helpers (validated mappings) =====================
__device__ __forceinline__ unsigned smem_u32(const void* p) {
    unsigned a;
    asm("{ .reg .u64 t; cvta.to.shared.u64 t, %1; cvt.u32.u64 %0, t; }" : "=r"(a) : "l"(p));
    return a;
}
__device__ __forceinline__ u64 ffma2(u64 a, u64 b, u64 c) {
    u64 d;
    asm("fma.rn.f32x2 %0, %1, %2, %3;" : "=l"(d) : "l"(a), "l"(b), "l"(c));
    return d;
}
__device__ __forceinline__ u64 fmul2(u64 a, u64 b) {
    u64 d;
    asm("mul.rn.f32x2 %0, %1, %2;" : "=l"(d) : "l"(a), "l"(b));
    return d;
}
__device__ __forceinline__ void ldmx4(unsigned* r, unsigned addr) {
    asm volatile("ldmatrix.sync.aligned.m8n8.x4.shared.b16 {%0,%1,%2,%3}, [%4];"
                 : "=r"(r[0]), "=r"(r[1]), "=r"(r[2]), "=r"(r[3]) : "r"(addr));
}
__device__ __forceinline__ void mma16816(float* d, const unsigned* a, const unsigned* b) {
    asm volatile("mma.sync.aligned.m16n8k16.row.col.f32.f16.f16.f32 "
                 "{%0,%1,%2,%3}, {%4,%5,%6,%7}, {%8,%9}, {%0,%1,%2,%3};"
                 : "+f"(d[0]), "+f"(d[1]), "+f"(d[2]), "+f"(d[3])
                 : "r"(a[0]), "r"(a[1]), "r"(a[2]), "r"(a[3]), "r"(b[0]), "r"(b[1]));
}

// ===================== prep: Wg fp16 hi/lo split + effective bias =====================
__global__ void prep_kernel(const float* __restrict__ Wg, const float* __restrict__ bg,
                            const float* __restrict__ Wm) {
    int e = blockIdx.x * blockDim.x + threadIdx.x;
    if (e < 16 * 32 * 64) {
        float v = Wg[e];
        __half h = __float2half_rn(v);
        g_wgh[e] = h;
        g_wgl[e] = __float2half_rn(v - __half2float(h));
    }
    if (e < NDIM) {
        int t = e >> 5;
        float s = Wm[t * 4] + Wm[t * 4 + 1] + Wm[t * 4 + 2] + Wm[t * 4 + 3];
        g_beff[e] = s * bg[e];
    }
}

// ===================== main kernel =====================
__global__ __launch_bounds__(THREADS, 1)
void ftok_kernel(const float* __restrict__ x, float* __restrict__ out,
                 const float* __restrict__ Wm) {
    extern __shared__ char smem[];
    const unsigned sb = smem_u32(smem);
    const int tid = threadIdx.x, wid = tid >> 5, l = tid & 31;
    const int mt  = blockIdx.x;
    // stage2 roles: token parity tg, row block wm (32 rows), n half wn (16 cols)
    const int tg  = wid & 1;
    const int wq  = wid >> 1;
    const int wm  = wq & 3;
    const int wn  = wq >> 2;
    // stage1 roles: row m, d-quarter dq (16 d's)
    const int m   = tid >> 2;
    const int dq  = tid & 3;

    // ---- one-time staging: Wg hi/lo (pitch 144), beff, Wm ----
    #pragma unroll
    for (int i = 0; i < 8; i++) {
        int u = tid + i * THREADS;            // 4096 uint4 per half
        int row = u >> 3, j = u & 7;          // row = t*32+n, k = 8j
        unsigned off = (unsigned)(row * PITCH + j * 16);
        *(uint4*)(smem + SM_WG + off)          = ((const uint4*)g_wgh)[u];
        *(uint4*)(smem + SM_WG + off + WGHALF) = ((const uint4*)g_wgl)[u];
    }
    ((float*)(smem + SM_BEFF))[tid] = g_beff[tid];
    if (tid < 64) ((float*)(smem + SM_WM))[tid] = Wm[tid];

    // ---- x -> registers: thread owns (m, dq): x[m][c*64 + dq*16 + 0..15] ----
    float4 xr[16];
    {
        const float* xrow = x + ((size_t)(mt * MTILE + m)) * KDIM + dq * 16;
        #pragma unroll
        for (int c = 0; c < 4; c++)
            #pragma unroll
            for (int e4 = 0; e4 < 4; e4++)
                xr[c * 4 + e4] = *(const float4*)(xrow + c * 64 + e4 * 4);
    }

    __syncthreads();

    const float4* wm_s  = (const float4*)(smem + SM_WM);
    const float*  beffs = (const float*)(smem + SM_BEFF);
    const unsigned ysts = (unsigned)(m * PITCH + dq * 32);
    const unsigned a_lane_off =
        (unsigned)((wm * 32 + (l & 15)) * PITCH + (l >> 4) * 16);
    const unsigned b_lane_off = (unsigned)(
        (wn * 16 + (l & 7) + ((l >> 4) & 1) * 8) * PITCH + ((l >> 3) & 1) * 16);

    // ---- stage1: produce y[t] (single fp16) into slot s ----
    auto stage1 = [&](int t, int s) {
        float4 wmv = wm_s[t];
        u64 wmd[4];
        {
            unsigned w0 = __float_as_uint(wmv.x), w1 = __float_as_uint(wmv.y);
            unsigned w2 = __float_as_uint(wmv.z), w3 = __float_as_uint(wmv.w);
            wmd[0] = ((u64)w0 << 32) | w0;  wmd[1] = ((u64)w1 << 32) | w1;
            wmd[2] = ((u64)w2 << 32) | w2;  wmd[3] = ((u64)w3 << 32) | w3;
        }
        unsigned hw[8];
        #pragma unroll
        for (int p = 0; p < 8; p++) {
            const int e4 = p >> 1, hi = p & 1;
            u64 x0 = hi ? ((const ulonglong2*)&xr[0 * 4 + e4])->y
                        : ((const ulonglong2*)&xr[0 * 4 + e4])->x;
            u64 x1 = hi ? ((const ulonglong2*)&xr[1 * 4 + e4])->y
                        : ((const ulonglong2*)&xr[1 * 4 + e4])->x;
            u64 x2 = hi ? ((const ulonglong2*)&xr[2 * 4 + e4])->y
                        : ((const ulonglong2*)&xr[2 * 4 + e4])->x;
            u64 x3 = hi ? ((const ulonglong2*)&xr[3 * 4 + e4])->y
                        : ((const ulonglong2*)&xr[3 * 4 + e4])->x;
            u64 acc = fmul2(wmd[0], x0);
            acc = ffma2(wmd[1], x1, acc);
            acc = ffma2(wmd[2], x2, acc);
            acc = ffma2(wmd[3], x3, acc);
            float ylo = __uint_as_float((unsigned)acc);
            float yhi = __uint_as_float((unsigned)(acc >> 32));
            __half2 h2 = __float22half2_rn(make_float2(ylo, yhi));
            hw[p] = *(unsigned*)&h2;
        }
        char* yb = smem + SM_Y + s * YTOK + ysts;
        *(uint4*)(yb)      = make_uint4(hw[0], hw[1], hw[2], hw[3]);
        *(uint4*)(yb + 16) = make_uint4(hw[4], hw[5], hw[6], hw[7]);
    };

    stage1(0, 0);
    stage1(1, 1);
    __syncthreads();

    #pragma unroll 1
    for (int i = 0; i < 8; i++) {
        const int sbase = (i & 1) * 2;
        if (i < 7) {
            stage1(2 * i + 2, sbase ^ 2);
            stage1(2 * i + 3, (sbase ^ 2) + 1);
        }

        // ---- stage2: token t = 2i+tg, [128m x 32n, K=64], y-fp16 x (Wh + Wl) ----
        const int t = 2 * i + tg;
        float acc[2][2][4];
        #pragma unroll
        for (int mb = 0; mb < 2; mb++)
            #pragma unroll
            for (int j = 0; j < 2; j++)
                #pragma unroll
                for (int q = 0; q < 4; q++) acc[mb][j][q] = 0.f;

        const unsigned ab = sb + SM_Y + (unsigned)((sbase + tg) * YTOK) + a_lane_off;
        const unsigned bb = sb + SM_WG + (unsigned)(t * 32 * PITCH) + b_lane_off;
        #pragma unroll
        for (int ks = 0; ks < 4; ks++) {
            unsigned bh[4], bl[4];
            ldmx4(bh, bb + ks * 32);
            ldmx4(bl, bb + ks * 32 + WGHALF);
            #pragma unroll
            for (int mb = 0; mb < 2; mb++) {
                unsigned ah[4];
                ldmx4(ah, ab + (unsigned)(mb * 16 * PITCH + ks * 32));
                mma16816(acc[mb][0], ah, bh);      // y * Wh, n8 tile 0
                mma16816(acc[mb][1], ah, bh + 2);  // y * Wh, n8 tile 1
                mma16816(acc[mb][0], ah, bl);      // y * Wl
                mma16816(acc[mb][1], ah, bl + 2);
            }
        }

        // ---- epilogue: bias + relu + store ----
        #pragma unroll
        for (int mb = 0; mb < 2; mb++) {
            const int r0 = wm * 32 + mb * 16 + (l >> 2);
            #pragma unroll
            for (int j = 0; j < 2; j++) {
                int n = wn * 16 + j * 8 + 2 * (l & 3);
                float2 bv = *(const float2*)(beffs + t * 32 + n);
                float2 v0, v1;
                v0.x = fmaxf(acc[mb][j][0] + bv.x, 0.f);
                v0.y = fmaxf(acc[mb][j][1] + bv.y, 0.f);
                v1.x = fmaxf(acc[mb][j][2] + bv.x, 0.f);
                v1.y = fmaxf(acc[mb][j][3] + bv.y, 0.f);
                size_t row = (size_t)(mt * MTILE + r0);
                *(float2*)(out + row * NDIM + t * 32 + n) = v0;
                *(float2*)(out + (row + 8) * NDIM + t * 32 + n) = v1;
            }
        }

        __syncthreads();
    }
}

// ===================== launch =====================
extern "C" void kernel_launch(void* const* d_in, const int* in_sizes, int n_in,
                              void* d_out, int out_size) {
    const float* x  = (const float*)d_in[0];
    const float* Wg = (const float*)d_in[1];
    const float* bg = (const float*)d_in[2];
    const float* Wm = (const float*)d_in[3];
    float* out = (float*)d_out;

    const int B   = in_sizes[0] / KDIM;      // 32768
    const int ntm = B / MTILE;               // 256

    prep_kernel<<<(16 * 32 * 64 + 255) / 256, 256>>>(Wg, bg, Wm);

    cudaFuncSetAttribute(ftok_kernel,
                         cudaFuncAttributeMaxDynamicSharedMemorySize, SMEM_TOTAL);
    ftok_kernel<<<ntm, THREADS, SMEM_TOTAL>>>(x, out, Wm);
}

// round 9
// speedup vs baseline: 2.5196x; 1.1699x over previous
#include <cuda_runtime.h>
#include <cuda_fp16.h>

// ===================== problem constants =====================
#define KDIM    256            // x row: c*64+d
#define NDIM    512            // t*32+o
#define MTILE   64
#define THREADS 256

// ===================== device scratch =====================
__device__ __half g_wgh[16 * 32 * 64];
__device__ float  g_beff[NDIM];

// ===================== smem layout =====================
#define PITCH    144                       // 64 fp16 (128B) + 16B pad: conflict-free
#define SM_WG    0                         // Wg fp16: 512 rows        (73728)
#define YTOK     (MTILE * PITCH)           // 9216 per token
#define SM_Y     73728                     // 4 token slots            (36864)
#define SM_BEFF  (SM_Y + 4 * YTOK)         // 110592
#define SM_WM    (SM_BEFF + NDIM * 4)      // 112640
#define SMEM_TOTAL (SM_WM + 64 * 4)        // 112896 (x2 CTA = 220.5 KB <= 228)

typedef unsigned long long u64;

// ===================== PTX helpers (validated mappings) =====================
__device__ __forceinline__ unsigned smem_u32(const void* p) {
    unsigned a;
    asm("{ .reg .u64 t; cvta.to.shared.u64 t, %1; cvt.u32.u64 %0, t; }" : "=r"(a) : "l"(p));
    return a;
}
__device__ __forceinline__ u64 ffma2(u64 a, u64 b, u64 c) {
    u64 d;
    asm("fma.rn.f32x2 %0, %1, %2, %3;" : "=l"(d) : "l"(a), "l"(b), "l"(c));
    return d;
}
__device__ __forceinline__ u64 fmul2(u64 a, u64 b) {
    u64 d;
    asm("mul.rn.f32x2 %0, %1, %2;" : "=l"(d) : "l"(a), "l"(b));
    return d;
}
__device__ __forceinline__ void ldmx4(unsigned* r, unsigned addr) {
    asm volatile("ldmatrix.sync.aligned.m8n8.x4.shared.b16 {%0,%1,%2,%3}, [%4];"
                 : "=r"(r[0]), "=r"(r[1]), "=r"(r[2]), "=r"(r[3]) : "r"(addr));
}
__device__ __forceinline__ void mma16816(float* d, const unsigned* a, const unsigned* b) {
    asm volatile("mma.sync.aligned.m16n8k16.row.col.f32.f16.f16.f32 "
                 "{%0,%1,%2,%3}, {%4,%5,%6,%7}, {%8,%9}, {%0,%1,%2,%3};"
                 : "+f"(d[0]), "+f"(d[1]), "+f"(d[2]), "+f"(d[3])
                 : "r"(a[0]), "r"(a[1]), "r"(a[2]), "r"(a[3]), "r"(b[0]), "r"(b[1]));
}

// ===================== prep: Wg fp16 + effective bias =====================
__global__ void prep_kernel(const float* __restrict__ Wg, const float* __restrict__ bg,
                            const float* __restrict__ Wm) {
    int e = blockIdx.x * blockDim.x + threadIdx.x;
    if (e < 16 * 32 * 64) g_wgh[e] = __float2half_rn(Wg[e]);
    if (e < NDIM) {
        int t = e >> 5;
        float s = Wm[t * 4] + Wm[t * 4 + 1] + Wm[t * 4 + 2] + Wm[t * 4 + 3];
        g_beff[e] = s * bg[e];
    }
}

// ===================== main kernel =====================
__global__ __launch_bounds__(THREADS, 2)
void ftok_kernel(const float* __restrict__ x, float* __restrict__ out,
                 const float* __restrict__ Wm) {
    extern __shared__ char smem[];
    const unsigned sb = smem_u32(smem);
    const int tid = threadIdx.x, wid = tid >> 5, l = tid & 31;
    const int mt  = blockIdx.x;
    // stage2 roles (8 warps): token parity tg, row block wm (32 rows), n half wn (16 cols)
    const int tg  = wid & 1;
    const int wq  = wid >> 1;
    const int wm  = wq & 1;
    const int wn  = wq >> 1;
    // stage1 roles: row m (0..63), d-quarter dq (16 d's)
    const int m   = tid >> 2;
    const int dq  = tid & 3;

    // ---- one-time staging: Wg fp16 (pitch 144), beff, Wm ----
    #pragma unroll
    for (int i = 0; i < 16; i++) {
        int u = tid + i * THREADS;            // 4096 uint4
        int row = u >> 3, j = u & 7;          // row = t*32+n, k = 8j
        unsigned off = (unsigned)(row * PITCH + j * 16);
        *(uint4*)(smem + SM_WG + off) = ((const uint4*)g_wgh)[u];
    }
    ((float*)(smem + SM_BEFF))[tid]           = g_beff[tid];
    ((float*)(smem + SM_BEFF))[tid + THREADS] = g_beff[tid + THREADS];
    if (tid < 64) ((float*)(smem + SM_WM))[tid] = Wm[tid];

    // ---- x -> registers: thread owns (m, dq): x[m][c*64 + dq*16 + 0..15] ----
    float4 xr[16];
    {
        const float* xrow = x + ((size_t)(mt * MTILE + m)) * KDIM + dq * 16;
        #pragma unroll
        for (int c = 0; c < 4; c++)
            #pragma unroll
            for (int e4 = 0; e4 < 4; e4++)
                xr[c * 4 + e4] = *(const float4*)(xrow + c * 64 + e4 * 4);
    }

    __syncthreads();

    const float4* wm_s  = (const float4*)(smem + SM_WM);
    const float*  beffs = (const float*)(smem + SM_BEFF);
    const unsigned ysts = (unsigned)(m * PITCH + dq * 32);
    const unsigned a_lane_off =
        (unsigned)((wm * 32 + (l & 15)) * PITCH + (l >> 4) * 16);
    const unsigned b_lane_off = (unsigned)(
        (wn * 16 + (l & 7) + ((l >> 4) & 1) * 8) * PITCH + ((l >> 3) & 1) * 16);

    // ---- stage1: produce y[t] (fp16) into slot s ----
    auto stage1 = [&](int t, int s) {
        float4 wmv = wm_s[t];
        u64 wmd[4];
        {
            unsigned w0 = __float_as_uint(wmv.x), w1 = __float_as_uint(wmv.y);
            unsigned w2 = __float_as_uint(wmv.z), w3 = __float_as_uint(wmv.w);
            wmd[0] = ((u64)w0 << 32) | w0;  wmd[1] = ((u64)w1 << 32) | w1;
            wmd[2] = ((u64)w2 << 32) | w2;  wmd[3] = ((u64)w3 << 32) | w3;
        }
        unsigned hw[8];
        #pragma unroll
        for (int p = 0; p < 8; p++) {
            const int e4 = p >> 1, hi = p & 1;
            u64 x0 = hi ? ((const ulonglong2*)&xr[0 * 4 + e4])->y
                        : ((const ulonglong2*)&xr[0 * 4 + e4])->x;
            u64 x1 = hi ? ((const ulonglong2*)&xr[1 * 4 + e4])->y
                        : ((const ulonglong2*)&xr[1 * 4 + e4])->x;
            u64 x2 = hi ? ((const ulonglong2*)&xr[2 * 4 + e4])->y
                        : ((const ulonglong2*)&xr[2 * 4 + e4])->x;
            u64 x3 = hi ? ((const ulonglong2*)&xr[3 * 4 + e4])->y
                        : ((const ulonglong2*)&xr[3 * 4 + e4])->x;
            u64 acc = fmul2(wmd[0], x0);
            acc = ffma2(wmd[1], x1, acc);
            acc = ffma2(wmd[2], x2, acc);
            acc = ffma2(wmd[3], x3, acc);
            float ylo = __uint_as_float((unsigned)acc);
            float yhi = __uint_as_float((unsigned)(acc >> 32));
            __half2 h2 = __float22half2_rn(make_float2(ylo, yhi));
            hw[p] = *(unsigned*)&h2;
        }
        char* yb = smem + SM_Y + s * YTOK + ysts;
        *(uint4*)(yb)      = make_uint4(hw[0], hw[1], hw[2], hw[3]);
        *(uint4*)(yb + 16) = make_uint4(hw[4], hw[5], hw[6], hw[7]);
    };

    stage1(0, 0);
    stage1(1, 1);
    __syncthreads();

    #pragma unroll 1
    for (int i = 0; i < 8; i++) {
        const int sbase = (i & 1) * 2;
        if (i < 7) {
            stage1(2 * i + 2, sbase ^ 2);
            stage1(2 * i + 3, (sbase ^ 2) + 1);
        }

        // ---- stage2: token t = 2i+tg, [64m x 32n, K=64], y-fp16 x W-fp16 ----
        const int t = 2 * i + tg;
        float acc[2][2][4];
        #pragma unroll
        for (int mb = 0; mb < 2; mb++)
            #pragma unroll
            for (int j = 0; j < 2; j++)
                #pragma unroll
                for (int q = 0; q < 4; q++) acc[mb][j][q] = 0.f;

        const unsigned ab = sb + SM_Y + (unsigned)((sbase + tg) * YTOK) + a_lane_off;
        const unsigned bb = sb + SM_WG + (unsigned)(t * 32 * PITCH) + b_lane_off;
        #pragma unroll
        for (int ks = 0; ks < 4; ks++) {
            unsigned bh[4];
            ldmx4(bh, bb + ks * 32);
            #pragma unroll
            for (int mb = 0; mb < 2; mb++) {
                unsigned ah[4];
                ldmx4(ah, ab + (unsigned)(mb * 16 * PITCH + ks * 32));
                mma16816(acc[mb][0], ah, bh);      // n8 tile 0
                mma16816(acc[mb][1], ah, bh + 2);  // n8 tile 1
            }
        }

        // ---- epilogue: bias + relu + store ----
        #pragma unroll
        for (int mb = 0; mb < 2; mb++) {
            const int r0 = wm * 32 + mb * 16 + (l >> 2);
            #pragma unroll
            for (int j = 0; j < 2; j++) {
                int n = wn * 16 + j * 8 + 2 * (l & 3);
                float2 bv = *(const float2*)(beffs + t * 32 + n);
                float2 v0, v1;
                v0.x = fmaxf(acc[mb][j][0] + bv.x, 0.f);
                v0.y = fmaxf(acc[mb][j][1] + bv.y, 0.f);
                v1.x = fmaxf(acc[mb][j][2] + bv.x, 0.f);
                v1.y = fmaxf(acc[mb][j][3] + bv.y, 0.f);
                size_t row = (size_t)(mt * MTILE + r0);
                *(float2*)(out + row * NDIM + t * 32 + n) = v0;
                *(float2*)(out + (row + 8) * NDIM + t * 32 + n) = v1;
            }
        }

        __syncthreads();
    }
}

// ===================== launch =====================
extern "C" void kernel_launch(void* const* d_in, const int* in_sizes, int n_in,
                              void* d_out, int out_size) {
    const float* x  = (const float*)d_in[0];
    const float* Wg = (const float*)d_in[1];
    const float* bg = (const float*)d_in[2];
    const float* Wm = (const float*)d_in[3];
    float* out = (float*)d_out;

    const int B   = in_sizes[0] / KDIM;      // 32768
    const int ntm = B / MTILE;               // 512

    prep_kernel<<<(16 * 32 * 64 + 255) / 256, 256>>>(Wg, bg, Wm);

    cudaFuncSetAttribute(ftok_kernel,
                         cudaFuncAttributeMaxDynamicSharedMemorySize, SMEM_TOTAL);
    ftok_kernel<<<ntm, THREADS, SMEM_TOTAL>>>(x, out, Wm);
}